// round 3
// baseline (speedup 1.0000x reference)
#include <cuda_runtime.h>
#include <math.h>

// Problem constants
#define BATCH 16
#define THW   2048
#define TF    2048
#define CDIM  512

// ---------------------------------------------------------------------------
// Scratch (device globals — no allocations allowed)
// ---------------------------------------------------------------------------
__device__ float g_qin[BATCH * THW * CDIM];       //  64 MB
__device__ float g_kp [BATCH * TF  * CDIM];       //  64 MB
__device__ float g_vp [BATCH * TF  * CDIM];       //  64 MB
__device__ float g_sc [(size_t)BATCH * THW * TF]; // 256 MB

// ---------------------------------------------------------------------------
// Generic batched SGEMM: C = A(MxK, lda) * B(KxN, ldb) [+ bias[n]] [+ resid]
// 128x128 block tile, BK=8, 8x8 per-thread microtile, 256 threads.
// Double-buffered shared memory pipeline.
// All dims assumed multiples of tile sizes (true for this problem).
// ---------------------------------------------------------------------------
#define BM 128
#define BN 128
#define BK 8
#define TM 8
#define TN 8

__global__ __launch_bounds__(256) void sgemm_kernel(
    const float* __restrict__ A, const float* __restrict__ B,
    const float* __restrict__ bias, const float* __restrict__ resid,
    float* __restrict__ C,
    int M, int N, int K, int lda, int ldb, int ldc,
    long long strideA, long long strideB, long long strideC, long long strideR)
{
    const long long bz = blockIdx.z;
    A += bz * strideA;
    B += bz * strideB;
    C += bz * strideC;
    const float* R = resid ? resid + bz * strideR : nullptr;

    __shared__ float As[2][BK][BM];
    __shared__ float Bs[2][BK][BN];

    const int tid = threadIdx.x;          // 0..255
    const int tx  = tid & 15;             // micro col group (0..15)
    const int ty  = tid >> 4;             // micro row group (0..15)
    const int row0 = blockIdx.y * BM;
    const int col0 = blockIdx.x * BN;

    // A tile load map: 128 rows x 8 cols; 2 threads per row (float4 each)
    const int arow = tid >> 1;            // 0..127
    const int acol = (tid & 1) * 4;       // 0 or 4
    // B tile load map: 8 rows x 128 cols; 32 threads per row (float4 each)
    const int brow = tid >> 5;            // 0..7
    const int bcol = (tid & 31) * 4;      // 0..124

    float acc[TM][TN];
    #pragma unroll
    for (int i = 0; i < TM; i++)
        #pragma unroll
        for (int j = 0; j < TN; j++) acc[i][j] = 0.0f;

    const float* Aload = A + (long long)(row0 + arow) * lda + acol;
    const float* Bload = B + (long long)brow * ldb + col0 + bcol;
    const long long bstep = (long long)BK * ldb;

    // Prologue: load tile 0 into buffer 0
    {
        float4 av = *reinterpret_cast<const float4*>(Aload);
        As[0][acol + 0][arow] = av.x;
        As[0][acol + 1][arow] = av.y;
        As[0][acol + 2][arow] = av.z;
        As[0][acol + 3][arow] = av.w;
        float4 bv = *reinterpret_cast<const float4*>(Bload);
        *reinterpret_cast<float4*>(&Bs[0][brow][bcol]) = bv;
    }
    __syncthreads();

    int buf = 0;
    for (int k0 = 0; k0 < K; k0 += BK) {
        // Prefetch next tile into registers (overlaps with math below)
        float4 av, bv;
        const bool has_next = (k0 + BK) < K;
        if (has_next) {
            av = *reinterpret_cast<const float4*>(Aload + (k0 + BK));
            bv = *reinterpret_cast<const float4*>(Bload + (long long)(k0 / BK + 1) * bstep);
        }

        // Compute on current buffer
        #pragma unroll
        for (int kk = 0; kk < BK; kk++) {
            float ra[TM], rb[TN];
            #pragma unroll
            for (int i = 0; i < TM; i++) ra[i] = As[buf][kk][ty * TM + i];
            #pragma unroll
            for (int j = 0; j < TN; j++) rb[j] = Bs[buf][kk][tx * TN + j];
            #pragma unroll
            for (int i = 0; i < TM; i++)
                #pragma unroll
                for (int j = 0; j < TN; j++)
                    acc[i][j] = fmaf(ra[i], rb[j], acc[i][j]);
        }

        // Store prefetched tile into the other buffer
        if (has_next) {
            const int nb = buf ^ 1;
            As[nb][acol + 0][arow] = av.x;
            As[nb][acol + 1][arow] = av.y;
            As[nb][acol + 2][arow] = av.z;
            As[nb][acol + 3][arow] = av.w;
            *reinterpret_cast<float4*>(&Bs[nb][brow][bcol]) = bv;
            __syncthreads();
            buf = nb;
        }
    }

    // Epilogue: optional bias (per output column) and residual add, vectorized.
    #pragma unroll
    for (int i = 0; i < TM; i++) {
        const int r = row0 + ty * TM + i;
        #pragma unroll
        for (int j = 0; j < TN; j += 4) {
            const int c = col0 + tx * TN + j;
            float4 v;
            v.x = acc[i][j + 0];
            v.y = acc[i][j + 1];
            v.z = acc[i][j + 2];
            v.w = acc[i][j + 3];
            if (bias) {
                const float4 bb = *reinterpret_cast<const float4*>(&bias[c]);
                v.x += bb.x; v.y += bb.y; v.z += bb.z; v.w += bb.w;
            }
            if (R) {
                const float4 rr = *reinterpret_cast<const float4*>(&R[(long long)r * ldc + c]);
                v.x += rr.x; v.y += rr.y; v.z += rr.z; v.w += rr.w;
            }
            *reinterpret_cast<float4*>(&C[(long long)r * ldc + c]) = v;
        }
    }
}

// ---------------------------------------------------------------------------
// Row softmax over length-TF rows (one block per row)
// ---------------------------------------------------------------------------
__global__ __launch_bounds__(256) void softmax_kernel(float* __restrict__ S)
{
    const long long row = blockIdx.x;
    float* p = S + row * (long long)TF;
    const int tid = threadIdx.x;

    __shared__ float red[32];

    // Each thread owns 8 contiguous float elements via two float4 loads
    float4 v0 = *reinterpret_cast<const float4*>(&p[tid * 8]);
    float4 v1 = *reinterpret_cast<const float4*>(&p[tid * 8 + 4]);

    // max
    float lmax = fmaxf(fmaxf(fmaxf(v0.x, v0.y), fmaxf(v0.z, v0.w)),
                       fmaxf(fmaxf(v1.x, v1.y), fmaxf(v1.z, v1.w)));
    #pragma unroll
    for (int o = 16; o; o >>= 1) lmax = fmaxf(lmax, __shfl_xor_sync(0xffffffffu, lmax, o));
    if ((tid & 31) == 0) red[tid >> 5] = lmax;
    __syncthreads();
    if (tid < 32) {
        float v = (tid < 8) ? red[tid] : -INFINITY;
        #pragma unroll
        for (int o = 4; o; o >>= 1) v = fmaxf(v, __shfl_xor_sync(0xffffffffu, v, o));
        if (tid == 0) red[0] = v;
    }
    __syncthreads();
    const float m = red[0];
    __syncthreads();

    // exp + sum
    v0.x = __expf(v0.x - m); v0.y = __expf(v0.y - m);
    v0.z = __expf(v0.z - m); v0.w = __expf(v0.w - m);
    v1.x = __expf(v1.x - m); v1.y = __expf(v1.y - m);
    v1.z = __expf(v1.z - m); v1.w = __expf(v1.w - m);
    float lsum = (v0.x + v0.y + v0.z + v0.w) + (v1.x + v1.y + v1.z + v1.w);
    #pragma unroll
    for (int o = 16; o; o >>= 1) lsum += __shfl_xor_sync(0xffffffffu, lsum, o);
    if ((tid & 31) == 0) red[tid >> 5] = lsum;
    __syncthreads();
    if (tid < 32) {
        float v = (tid < 8) ? red[tid] : 0.0f;
        #pragma unroll
        for (int o = 4; o; o >>= 1) v += __shfl_xor_sync(0xffffffffu, v, o);
        if (tid == 0) red[0] = v;
    }
    __syncthreads();
    const float inv = 1.0f / red[0];
    v0.x *= inv; v0.y *= inv; v0.z *= inv; v0.w *= inv;
    v1.x *= inv; v1.y *= inv; v1.z *= inv; v1.w *= inv;
    *reinterpret_cast<float4*>(&p[tid * 8])     = v0;
    *reinterpret_cast<float4*>(&p[tid * 8 + 4]) = v1;
}

// ---------------------------------------------------------------------------
// kernel_launch
// ---------------------------------------------------------------------------
extern "C" void kernel_launch(void* const* d_in, const int* in_sizes, int n_in,
                              void* d_out, int out_size)
{
    const float* q  = (const float*)d_in[0];  // [B, THW, DQ]
    const float* k  = (const float*)d_in[1];  // [B, TF, DK]
    const float* Wq = (const float*)d_in[2];  // [DQ, C]
    const float* bq = (const float*)d_in[3];  // [C]
    const float* Wk = (const float*)d_in[4];
    const float* bk = (const float*)d_in[5];
    const float* Wv = (const float*)d_in[6];
    const float* bv = (const float*)d_in[7];
    float* out = (float*)d_out;               // [B, THW*C]

    void* p;
    cudaGetSymbolAddress(&p, g_qin); float* qin = (float*)p;
    cudaGetSymbolAddress(&p, g_kp);  float* kp  = (float*)p;
    cudaGetSymbolAddress(&p, g_vp);  float* vp  = (float*)p;
    cudaGetSymbolAddress(&p, g_sc);  float* sc  = (float*)p;

    const dim3 blk(256);

    // --- Projections: [B*THW, 512] x [512, 512] + bias ---
    {
        const int M = BATCH * THW, N = CDIM, K = CDIM;
        const dim3 grid(N / BN, M / BM, 1);
        sgemm_kernel<<<grid, blk>>>(q, Wq, bq, nullptr, qin,
                                    M, N, K, CDIM, CDIM, CDIM, 0, 0, 0, 0);
        sgemm_kernel<<<grid, blk>>>(k, Wk, bk, nullptr, kp,
                                    M, N, K, CDIM, CDIM, CDIM, 0, 0, 0, 0);
        sgemm_kernel<<<grid, blk>>>(k, Wv, bv, nullptr, vp,
                                    M, N, K, CDIM, CDIM, CDIM, 0, 0, 0, 0);
    }

    // --- Scores: per batch, qin[b] (2048x512) x kin[b] (512x2048 raw view of kp) ---
    {
        const int M = THW, N = TF, K = CDIM;
        const dim3 grid(N / BN, M / BM, BATCH);
        sgemm_kernel<<<grid, blk>>>(qin, kp, nullptr, nullptr, sc,
                                    M, N, K, /*lda*/CDIM, /*ldb*/TF, /*ldc*/TF,
                                    (long long)THW * CDIM,
                                    (long long)TF * CDIM,
                                    (long long)THW * TF, 0);
    }

    // --- Softmax over TF for each of B*THW rows ---
    softmax_kernel<<<BATCH * THW, blk>>>(sc);

    // --- Output: per batch, attn (2048x2048) x vin (2048x512) + qin residual ---
    {
        const int M = THW, N = CDIM, K = TF;
        const dim3 grid(N / BN, M / BM, BATCH);
        sgemm_kernel<<<grid, blk>>>(sc, vp, nullptr, qin, out,
                                    M, N, K, /*lda*/TF, /*ldb*/CDIM, /*ldc*/CDIM,
                                    (long long)THW * TF,
                                    (long long)TF * CDIM,
                                    (long long)THW * CDIM,
                                    (long long)THW * CDIM);
    }
}

// round 4
// speedup vs baseline: 2.3211x; 2.3211x over previous
#include <cuda_runtime.h>
#include <cuda_bf16.h>
#include <math.h>
#include <stdint.h>

// Problem constants
#define BATCH 16
#define THW   2048
#define TF    2048
#define CDIM  512

// ---------------------------------------------------------------------------
// Scratch (device globals — no allocations allowed)
// ---------------------------------------------------------------------------
__device__ float g_qin[BATCH * THW * CDIM];       //  64 MB
__device__ float g_kp [BATCH * TF  * CDIM];       //  64 MB
__device__ float g_vp [BATCH * TF  * CDIM];       //  64 MB
__device__ float g_sc [(size_t)BATCH * THW * TF]; // 256 MB

// ---------------------------------------------------------------------------
// bf16-split tensor-core GEMM
//   C = A(MxK fp32, lda) * B(KxN fp32, ldb) [+ bias] [+ resid]
//   A,B split into hi/lo bf16; acc = hi*hi + hi*lo + lo*hi (fp32 accum).
// Block tile 128x128x32, 256 threads = 8 warps (2m x 4n), warp tile 64x32.
// ---------------------------------------------------------------------------
#define BM 128
#define BN 128
#define BKF 32
#define LDA_S 40     // padded A row stride (bf16 elems) — conflict-free ldmatrix
#define LDB_S 136    // padded B row stride (bf16 elems)
#define A_TILE (BM * LDA_S)   // 5120 bf16
#define B_TILE (BKF * LDB_S)  // 4352 bf16
#define SMEM_BYTES ((2 * A_TILE * 2 + 2 * B_TILE * 2) * 2)  // 75776 bytes

__device__ __forceinline__ void ldsm4(uint32_t* r, uint32_t addr) {
    asm volatile("ldmatrix.sync.aligned.m8n8.x4.shared.b16 {%0,%1,%2,%3}, [%4];\n"
                 : "=r"(r[0]), "=r"(r[1]), "=r"(r[2]), "=r"(r[3]) : "r"(addr));
}
__device__ __forceinline__ void ldsm4t(uint32_t* r, uint32_t addr) {
    asm volatile("ldmatrix.sync.aligned.m8n8.x4.trans.shared.b16 {%0,%1,%2,%3}, [%4];\n"
                 : "=r"(r[0]), "=r"(r[1]), "=r"(r[2]), "=r"(r[3]) : "r"(addr));
}
__device__ __forceinline__ void mma16816(float* c, const uint32_t* a, const uint32_t* b) {
    asm volatile("mma.sync.aligned.m16n8k16.row.col.f32.bf16.bf16.f32 "
                 "{%0,%1,%2,%3},{%4,%5,%6,%7},{%8,%9},{%0,%1,%2,%3};\n"
                 : "+f"(c[0]), "+f"(c[1]), "+f"(c[2]), "+f"(c[3])
                 : "r"(a[0]), "r"(a[1]), "r"(a[2]), "r"(a[3]), "r"(b[0]), "r"(b[1]));
}

__device__ __forceinline__ void cvt_store4(__nv_bfloat16* hi, __nv_bfloat16* lo,
                                           int off, float4 v) {
    __nv_bfloat16 h0 = __float2bfloat16(v.x);
    __nv_bfloat16 h1 = __float2bfloat16(v.y);
    __nv_bfloat16 h2 = __float2bfloat16(v.z);
    __nv_bfloat16 h3 = __float2bfloat16(v.w);
    __nv_bfloat16 l0 = __float2bfloat16(v.x - __bfloat162float(h0));
    __nv_bfloat16 l1 = __float2bfloat16(v.y - __bfloat162float(h1));
    __nv_bfloat16 l2 = __float2bfloat16(v.z - __bfloat162float(h2));
    __nv_bfloat16 l3 = __float2bfloat16(v.w - __bfloat162float(h3));
    *reinterpret_cast<__nv_bfloat162*>(hi + off)     = __halves2bfloat162(h0, h1);
    *reinterpret_cast<__nv_bfloat162*>(hi + off + 2) = __halves2bfloat162(h2, h3);
    *reinterpret_cast<__nv_bfloat162*>(lo + off)     = __halves2bfloat162(l0, l1);
    *reinterpret_cast<__nv_bfloat162*>(lo + off + 2) = __halves2bfloat162(l2, l3);
}

__global__ __launch_bounds__(256, 1) void mma_gemm(
    const float* __restrict__ A, const float* __restrict__ B,
    const float* __restrict__ bias, const float* __restrict__ resid,
    float* __restrict__ C,
    int K, int lda, int ldb, int ldc,
    long long strideA, long long strideB, long long strideC, long long strideR)
{
    extern __shared__ __nv_bfloat16 sm[];
    __nv_bfloat16* Ah = sm;                    // [2][A_TILE]
    __nv_bfloat16* Al = Ah + 2 * A_TILE;
    __nv_bfloat16* Bh = Al + 2 * A_TILE;       // [2][B_TILE]
    __nv_bfloat16* Bl = Bh + 2 * B_TILE;

    const long long bz = blockIdx.z;
    A += bz * strideA;
    B += bz * strideB;
    C += bz * strideC;
    const float* R = resid ? resid + bz * strideR : nullptr;

    const int tid  = threadIdx.x;
    const int warp = tid >> 5;
    const int lane = tid & 31;
    const int wm = warp >> 2;        // 0..1  (64 rows each)
    const int wn = warp & 3;         // 0..3  (32 cols each)
    const int g   = lane >> 2;
    const int tig = lane & 3;

    const int row0 = blockIdx.y * BM;
    const int col0 = blockIdx.x * BN;

    // Global load maps (4 float4 per thread per operand per tile)
    const int arow = tid >> 3;           // 0..31, +32 per iter
    const int acol = (tid & 7) * 4;      // 0..28
    const int brow = tid >> 5;           // 0..7,  +8 per iter
    const int bcol = (tid & 31) * 4;     // 0..124

    // ldmatrix lane-address components
    const int a_r = wm * 64 + (lane & 15);
    const int a_c = (lane >> 4) * 8;
    const int b_r = (lane & 15);
    const int b_c = wn * 32 + ((lane & 16) ? 8 : 0);

    float acc[4][4][4];
    #pragma unroll
    for (int i = 0; i < 4; i++)
        #pragma unroll
        for (int j = 0; j < 4; j++)
            #pragma unroll
            for (int l = 0; l < 4; l++) acc[i][j][l] = 0.0f;

    const uint32_t Ah_s = (uint32_t)__cvta_generic_to_shared(Ah);
    const uint32_t Al_s = (uint32_t)__cvta_generic_to_shared(Al);
    const uint32_t Bh_s = (uint32_t)__cvta_generic_to_shared(Bh);
    const uint32_t Bl_s = (uint32_t)__cvta_generic_to_shared(Bl);

    // ---- prologue: tile 0 -> buffer 0 ----
    {
        #pragma unroll
        for (int i = 0; i < 4; i++) {
            float4 v = *reinterpret_cast<const float4*>(
                A + (long long)(row0 + arow + 32 * i) * lda + acol);
            cvt_store4(Ah, Al, (arow + 32 * i) * LDA_S + acol, v);
        }
        #pragma unroll
        for (int i = 0; i < 4; i++) {
            float4 v = *reinterpret_cast<const float4*>(
                B + (long long)(brow + 8 * i) * ldb + col0 + bcol);
            cvt_store4(Bh, Bl, (brow + 8 * i) * LDB_S + bcol, v);
        }
    }
    __syncthreads();

    int buf = 0;
    for (int k0 = 0; k0 < K; k0 += BKF) {
        const bool has_next = (k0 + BKF) < K;
        float4 pa[4], pb[4];
        if (has_next) {
            #pragma unroll
            for (int i = 0; i < 4; i++)
                pa[i] = *reinterpret_cast<const float4*>(
                    A + (long long)(row0 + arow + 32 * i) * lda + (k0 + BKF + acol));
            #pragma unroll
            for (int i = 0; i < 4; i++)
                pb[i] = *reinterpret_cast<const float4*>(
                    B + (long long)(k0 + BKF + brow + 8 * i) * ldb + col0 + bcol);
        }

        // ---- compute on current buffer ----
        const uint32_t ah0 = Ah_s + buf * (A_TILE * 2);
        const uint32_t al0 = Al_s + buf * (A_TILE * 2);
        const uint32_t bh0 = Bh_s + buf * (B_TILE * 2);
        const uint32_t bl0 = Bl_s + buf * (B_TILE * 2);

        #pragma unroll
        for (int ks = 0; ks < 2; ks++) {
            uint32_t fah[4][4], fal[4][4], fbh[4][2], fbl[4][2];
            // A hi fragments (4 m-tiles)
            #pragma unroll
            for (int mt = 0; mt < 4; mt++)
                ldsm4(fah[mt], ah0 + 2 * ((a_r + mt * 16) * LDA_S + a_c + ks * 16));
            // B hi fragments (4 n-tiles via two x4.trans)
            {
                uint32_t t[4];
                ldsm4t(t, bh0 + 2 * ((ks * 16 + b_r) * LDB_S + b_c));
                fbh[0][0] = t[0]; fbh[0][1] = t[1]; fbh[1][0] = t[2]; fbh[1][1] = t[3];
                ldsm4t(t, bh0 + 2 * ((ks * 16 + b_r) * LDB_S + b_c + 16));
                fbh[2][0] = t[0]; fbh[2][1] = t[1]; fbh[3][0] = t[2]; fbh[3][1] = t[3];
            }
            // P1: hi * hi
            #pragma unroll
            for (int mt = 0; mt < 4; mt++)
                #pragma unroll
                for (int nt = 0; nt < 4; nt++)
                    mma16816(acc[mt][nt], fah[mt], fbh[nt]);
            // B lo fragments
            {
                uint32_t t[4];
                ldsm4t(t, bl0 + 2 * ((ks * 16 + b_r) * LDB_S + b_c));
                fbl[0][0] = t[0]; fbl[0][1] = t[1]; fbl[1][0] = t[2]; fbl[1][1] = t[3];
                ldsm4t(t, bl0 + 2 * ((ks * 16 + b_r) * LDB_S + b_c + 16));
                fbl[2][0] = t[0]; fbl[2][1] = t[1]; fbl[3][0] = t[2]; fbl[3][1] = t[3];
            }
            // P2: hi * lo
            #pragma unroll
            for (int mt = 0; mt < 4; mt++)
                #pragma unroll
                for (int nt = 0; nt < 4; nt++)
                    mma16816(acc[mt][nt], fah[mt], fbl[nt]);
            // A lo fragments
            #pragma unroll
            for (int mt = 0; mt < 4; mt++)
                ldsm4(fal[mt], al0 + 2 * ((a_r + mt * 16) * LDA_S + a_c + ks * 16));
            // P3: lo * hi
            #pragma unroll
            for (int mt = 0; mt < 4; mt++)
                #pragma unroll
                for (int nt = 0; nt < 4; nt++)
                    mma16816(acc[mt][nt], fal[mt], fbh[nt]);
        }

        if (has_next) {
            const int nb = buf ^ 1;
            __nv_bfloat16* ahn = Ah + nb * A_TILE;
            __nv_bfloat16* aln = Al + nb * A_TILE;
            __nv_bfloat16* bhn = Bh + nb * B_TILE;
            __nv_bfloat16* bln = Bl + nb * B_TILE;
            #pragma unroll
            for (int i = 0; i < 4; i++)
                cvt_store4(ahn, aln, (arow + 32 * i) * LDA_S + acol, pa[i]);
            #pragma unroll
            for (int i = 0; i < 4; i++)
                cvt_store4(bhn, bln, (brow + 8 * i) * LDB_S + bcol, pb[i]);
            __syncthreads();
            buf = nb;
        }
    }

    // ---- epilogue ----
    #pragma unroll
    for (int mt = 0; mt < 4; mt++) {
        #pragma unroll
        for (int nt = 0; nt < 4; nt++) {
            const int r = row0 + wm * 64 + mt * 16 + g;
            const int c = col0 + wn * 32 + nt * 8 + 2 * tig;
            float2 v0 = make_float2(acc[mt][nt][0], acc[mt][nt][1]);
            float2 v1 = make_float2(acc[mt][nt][2], acc[mt][nt][3]);
            if (bias) {
                const float b0 = bias[c], b1 = bias[c + 1];
                v0.x += b0; v0.y += b1;
                v1.x += b0; v1.y += b1;
            }
            if (R) {
                const float2 r0v = *reinterpret_cast<const float2*>(&R[(long long)r * ldc + c]);
                const float2 r1v = *reinterpret_cast<const float2*>(&R[(long long)(r + 8) * ldc + c]);
                v0.x += r0v.x; v0.y += r0v.y;
                v1.x += r1v.x; v1.y += r1v.y;
            }
            *reinterpret_cast<float2*>(&C[(long long)r * ldc + c]) = v0;
            *reinterpret_cast<float2*>(&C[(long long)(r + 8) * ldc + c]) = v1;
        }
    }
}

// ---------------------------------------------------------------------------
// Row softmax over length-TF rows (one block per row, 256 threads x 8 elems)
// ---------------------------------------------------------------------------
__global__ __launch_bounds__(256) void softmax_kernel(float* __restrict__ S)
{
    const long long row = blockIdx.x;
    float* p = S + row * (long long)TF;
    const int tid = threadIdx.x;

    __shared__ float red[32];

    float4 v0 = *reinterpret_cast<const float4*>(&p[tid * 8]);
    float4 v1 = *reinterpret_cast<const float4*>(&p[tid * 8 + 4]);

    float lmax = fmaxf(fmaxf(fmaxf(v0.x, v0.y), fmaxf(v0.z, v0.w)),
                       fmaxf(fmaxf(v1.x, v1.y), fmaxf(v1.z, v1.w)));
    #pragma unroll
    for (int o = 16; o; o >>= 1) lmax = fmaxf(lmax, __shfl_xor_sync(0xffffffffu, lmax, o));
    if ((tid & 31) == 0) red[tid >> 5] = lmax;
    __syncthreads();
    if (tid < 32) {
        float v = (tid < 8) ? red[tid] : -INFINITY;
        #pragma unroll
        for (int o = 4; o; o >>= 1) v = fmaxf(v, __shfl_xor_sync(0xffffffffu, v, o));
        if (tid == 0) red[0] = v;
    }
    __syncthreads();
    const float m = red[0];
    __syncthreads();

    v0.x = __expf(v0.x - m); v0.y = __expf(v0.y - m);
    v0.z = __expf(v0.z - m); v0.w = __expf(v0.w - m);
    v1.x = __expf(v1.x - m); v1.y = __expf(v1.y - m);
    v1.z = __expf(v1.z - m); v1.w = __expf(v1.w - m);
    float lsum = (v0.x + v0.y + v0.z + v0.w) + (v1.x + v1.y + v1.z + v1.w);
    #pragma unroll
    for (int o = 16; o; o >>= 1) lsum += __shfl_xor_sync(0xffffffffu, lsum, o);
    if ((tid & 31) == 0) red[tid >> 5] = lsum;
    __syncthreads();
    if (tid < 32) {
        float v = (tid < 8) ? red[tid] : 0.0f;
        #pragma unroll
        for (int o = 4; o; o >>= 1) v += __shfl_xor_sync(0xffffffffu, v, o);
        if (tid == 0) red[0] = v;
    }
    __syncthreads();
    const float inv = 1.0f / red[0];
    v0.x *= inv; v0.y *= inv; v0.z *= inv; v0.w *= inv;
    v1.x *= inv; v1.y *= inv; v1.z *= inv; v1.w *= inv;
    *reinterpret_cast<float4*>(&p[tid * 8])     = v0;
    *reinterpret_cast<float4*>(&p[tid * 8 + 4]) = v1;
}

// ---------------------------------------------------------------------------
// kernel_launch
// ---------------------------------------------------------------------------
extern "C" void kernel_launch(void* const* d_in, const int* in_sizes, int n_in,
                              void* d_out, int out_size)
{
    const float* q  = (const float*)d_in[0];  // [B, THW, DQ]
    const float* k  = (const float*)d_in[1];  // [B, TF, DK]
    const float* Wq = (const float*)d_in[2];  // [DQ, C]
    const float* bq = (const float*)d_in[3];  // [C]
    const float* Wk = (const float*)d_in[4];
    const float* bk = (const float*)d_in[5];
    const float* Wv = (const float*)d_in[6];
    const float* bv = (const float*)d_in[7];
    float* out = (float*)d_out;               // [B, THW*C]

    void* p;
    cudaGetSymbolAddress(&p, g_qin); float* qin = (float*)p;
    cudaGetSymbolAddress(&p, g_kp);  float* kp  = (float*)p;
    cudaGetSymbolAddress(&p, g_vp);  float* vp  = (float*)p;
    cudaGetSymbolAddress(&p, g_sc);  float* sc  = (float*)p;

    cudaFuncSetAttribute(mma_gemm, cudaFuncAttributeMaxDynamicSharedMemorySize,
                         SMEM_BYTES);

    const dim3 blk(256);

    // --- Projections: [B*THW, 512] x [512, 512] + bias ---
    {
        const dim3 grid(CDIM / BN, (BATCH * THW) / BM, 1);
        mma_gemm<<<grid, blk, SMEM_BYTES>>>(q, Wq, bq, nullptr, qin,
                                            CDIM, CDIM, CDIM, CDIM, 0, 0, 0, 0);
        mma_gemm<<<grid, blk, SMEM_BYTES>>>(k, Wk, bk, nullptr, kp,
                                            CDIM, CDIM, CDIM, CDIM, 0, 0, 0, 0);
        mma_gemm<<<grid, blk, SMEM_BYTES>>>(k, Wv, bv, nullptr, vp,
                                            CDIM, CDIM, CDIM, CDIM, 0, 0, 0, 0);
    }

    // --- Scores: per batch, qin[b] (2048x512) x kp[b] viewed (512x2048, ldb=TF) ---
    {
        const dim3 grid(TF / BN, THW / BM, BATCH);
        mma_gemm<<<grid, blk, SMEM_BYTES>>>(qin, kp, nullptr, nullptr, sc,
                                            CDIM, CDIM, TF, TF,
                                            (long long)THW * CDIM,
                                            (long long)TF * CDIM,
                                            (long long)THW * TF, 0);
    }

    // --- Softmax over TF for each of B*THW rows ---
    softmax_kernel<<<BATCH * THW, blk>>>(sc);

    // --- Output: per batch, attn (2048x2048) x vp (2048x512) + qin residual ---
    {
        const dim3 grid(CDIM / BN, THW / BM, BATCH);
        mma_gemm<<<grid, blk, SMEM_BYTES>>>(sc, vp, nullptr, qin, out,
                                            TF, TF, CDIM, CDIM,
                                            (long long)THW * TF,
                                            (long long)TF * CDIM,
                                            (long long)THW * CDIM,
                                            (long long)THW * CDIM);
    }
}